// round 1
// baseline (speedup 1.0000x reference)
#include <cuda_runtime.h>

#define NN 100000
#define EE 1600000
#define DD 128

// Scratch (allocation-free: device globals)
__device__ float g_aggr[(size_t)NN * DD];
__device__ float g_h[(size_t)NN * DD];

// ---------------------------------------------------------------------------
// Zero the aggregation buffer (float4 stores)
// ---------------------------------------------------------------------------
__global__ void zero_kernel(int n4) {
    int i = blockIdx.x * blockDim.x + threadIdx.x;
    if (i < n4) reinterpret_cast<float4*>(g_aggr)[i] = make_float4(0.f, 0.f, 0.f, 0.f);
}

// ---------------------------------------------------------------------------
// Edge phase: one warp per edge. msg = relu(x[src] + e_attr); red-add to aggr[dst].
// Each lane handles 4 floats (full 512B row per warp), vector red.global.add.v4.f32.
// ---------------------------------------------------------------------------
__global__ __launch_bounds__(256) void edge_kernel(const float* __restrict__ x,
                                                   const int* __restrict__ ei,
                                                   const float* __restrict__ ea) {
    int e = blockIdx.x * 8 + (threadIdx.x >> 5);
    if (e >= EE) return;
    int lane = threadIdx.x & 31;
    int src = __ldg(ei + e);
    int dst = __ldg(ei + EE + e);

    float4 xv = __ldg(reinterpret_cast<const float4*>(x) + src * 32 + lane);
    float4 ev = __ldg(reinterpret_cast<const float4*>(ea) + e * 32 + lane);
    float4 m;
    m.x = fmaxf(xv.x + ev.x, 0.f);
    m.y = fmaxf(xv.y + ev.y, 0.f);
    m.z = fmaxf(xv.z + ev.z, 0.f);
    m.w = fmaxf(xv.w + ev.w, 0.f);

    float* a = g_aggr + (size_t)dst * DD + lane * 4;
    asm volatile("red.global.add.v4.f32 [%0], {%1, %2, %3, %4};"
                 :: "l"(a), "f"(m.x), "f"(m.y), "f"(m.z), "f"(m.w)
                 : "memory");
}

// ---------------------------------------------------------------------------
// Register-tiled fp32 GEMM: out[N,128] = act(A' @ W + bias)
//   FUSE_Z:  A' = (1+eps)*X + A   (computed during A-tile load)
//   RELU:    apply relu in epilogue
// Block: 256 threads, 128x128 output tile, 8x8 per-thread micro-tile.
// Thread (tr,tc): rows tr*8..tr*8+7, cols {tc*4..tc*4+3} U {64+tc*4..64+tc*4+3}
//   -> all smem traffic is conflict-free LDS.128 (A-frag loads are phase-uniform
//      broadcasts; B-frag phases hit 8 distinct 16B slots).
// ---------------------------------------------------------------------------
template <bool FUSE_Z, bool RELU>
__global__ __launch_bounds__(256, 1) void gemm128(
    const float* __restrict__ A,
    const float* __restrict__ X,
    const float* __restrict__ epsp,
    const float* __restrict__ W,
    const float* __restrict__ bias,
    float* __restrict__ out,
    int nrows) {
    extern __shared__ float smem[];
    float* As = smem;              // [128][128]
    float* Ws = smem + 128 * 128;  // [128][128]

    int tid = threadIdx.x;
    int row0 = blockIdx.x * 128;
    float epsv = 0.f;
    if (FUSE_Z) epsv = 1.0f + __ldg(epsp);

    // Load W tile: 4096 float4, coalesced
    #pragma unroll
    for (int t = 0; t < 16; t++) {
        int i = tid + t * 256;
        reinterpret_cast<float4*>(Ws)[i] = __ldg(reinterpret_cast<const float4*>(W) + i);
    }
    // Load A tile (with optional fused z = (1+eps)*x + aggr), zero-fill OOB rows
    #pragma unroll
    for (int t = 0; t < 16; t++) {
        int i = tid + t * 256;
        int r = i >> 5;        // row within tile (32 float4 per row)
        int c4 = i & 31;
        int gr = row0 + r;
        float4 v;
        if (gr < nrows) {
            v = __ldg(reinterpret_cast<const float4*>(A) + gr * 32 + c4);
            if (FUSE_Z) {
                float4 xv = __ldg(reinterpret_cast<const float4*>(X) + gr * 32 + c4);
                v.x += epsv * xv.x;
                v.y += epsv * xv.y;
                v.z += epsv * xv.z;
                v.w += epsv * xv.w;
            }
        } else {
            v = make_float4(0.f, 0.f, 0.f, 0.f);
        }
        reinterpret_cast<float4*>(As)[i] = v;
    }
    __syncthreads();

    int tr = tid >> 4;  // 0..15
    int tc = tid & 15;  // 0..15

    float acc[8][8];
    #pragma unroll
    for (int i = 0; i < 8; i++)
        #pragma unroll
        for (int j = 0; j < 8; j++) acc[i][j] = 0.f;

    for (int k0 = 0; k0 < 128; k0 += 4) {
        float4 a[8];
        #pragma unroll
        for (int i = 0; i < 8; i++)
            a[i] = *reinterpret_cast<const float4*>(&As[(tr * 8 + i) * 128 + k0]);

        float4 b[4][2];
        #pragma unroll
        for (int kk = 0; kk < 4; kk++) {
            b[kk][0] = *reinterpret_cast<const float4*>(&Ws[(k0 + kk) * 128 + tc * 4]);
            b[kk][1] = *reinterpret_cast<const float4*>(&Ws[(k0 + kk) * 128 + 64 + tc * 4]);
        }

        #pragma unroll
        for (int kk = 0; kk < 4; kk++) {
            #pragma unroll
            for (int i = 0; i < 8; i++) {
                float av = (kk == 0) ? a[i].x : (kk == 1) ? a[i].y : (kk == 2) ? a[i].z : a[i].w;
                acc[i][0] += av * b[kk][0].x;
                acc[i][1] += av * b[kk][0].y;
                acc[i][2] += av * b[kk][0].z;
                acc[i][3] += av * b[kk][0].w;
                acc[i][4] += av * b[kk][1].x;
                acc[i][5] += av * b[kk][1].y;
                acc[i][6] += av * b[kk][1].z;
                acc[i][7] += av * b[kk][1].w;
            }
        }
    }

    float4 bv0 = __ldg(reinterpret_cast<const float4*>(bias) + tc);
    float4 bv1 = __ldg(reinterpret_cast<const float4*>(bias) + 16 + tc);

    #pragma unroll
    for (int i = 0; i < 8; i++) {
        int gr = row0 + tr * 8 + i;
        if (gr < nrows) {
            float4 o0, o1;
            o0.x = acc[i][0] + bv0.x;
            o0.y = acc[i][1] + bv0.y;
            o0.z = acc[i][2] + bv0.z;
            o0.w = acc[i][3] + bv0.w;
            o1.x = acc[i][4] + bv1.x;
            o1.y = acc[i][5] + bv1.y;
            o1.z = acc[i][6] + bv1.z;
            o1.w = acc[i][7] + bv1.w;
            if (RELU) {
                o0.x = fmaxf(o0.x, 0.f); o0.y = fmaxf(o0.y, 0.f);
                o0.z = fmaxf(o0.z, 0.f); o0.w = fmaxf(o0.w, 0.f);
                o1.x = fmaxf(o1.x, 0.f); o1.y = fmaxf(o1.y, 0.f);
                o1.z = fmaxf(o1.z, 0.f); o1.w = fmaxf(o1.w, 0.f);
            }
            reinterpret_cast<float4*>(out)[gr * 32 + tc] = o0;
            reinterpret_cast<float4*>(out)[gr * 32 + 16 + tc] = o1;
        }
    }
}

// ---------------------------------------------------------------------------
extern "C" void kernel_launch(void* const* d_in, const int* in_sizes, int n_in,
                              void* d_out, int out_size) {
    const float* x   = (const float*)d_in[0];
    const int*   ei  = (const int*)d_in[1];
    const float* ea  = (const float*)d_in[2];
    const float* eps = (const float*)d_in[3];
    const float* W1  = (const float*)d_in[4];
    const float* b1  = (const float*)d_in[5];
    const float* W2  = (const float*)d_in[6];
    const float* b2  = (const float*)d_in[7];
    float* out = (float*)d_out;

    float *aggr_p, *h_p;
    cudaGetSymbolAddress((void**)&aggr_p, g_aggr);
    cudaGetSymbolAddress((void**)&h_p, g_h);

    const int SMEM = 2 * 128 * 128 * (int)sizeof(float);  // 131072
    cudaFuncSetAttribute(gemm128<true, true>,
                         cudaFuncAttributeMaxDynamicSharedMemorySize, SMEM);
    cudaFuncSetAttribute(gemm128<false, false>,
                         cudaFuncAttributeMaxDynamicSharedMemorySize, SMEM);

    // 1) zero accumulator
    int n4 = NN * DD / 4;  // 3.2M float4
    zero_kernel<<<(n4 + 255) / 256, 256>>>(n4);

    // 2) edge scatter (warp per edge)
    edge_kernel<<<EE / 8, 256>>>(x, ei, ea);

    // 3) MLP layer 1: h = relu(((1+eps)x + aggr) @ W1 + b1)
    int nblk = (NN + 127) / 128;
    gemm128<true, true><<<nblk, 256, SMEM>>>(aggr_p, x, eps, W1, b1, h_p, NN);

    // 4) MLP layer 2: out = h @ W2 + b2
    gemm128<false, false><<<nblk, 256, SMEM>>>(h_p, nullptr, nullptr, W2, b2, out, NN);
}

// round 2
// speedup vs baseline: 1.0325x; 1.0325x over previous
#include <cuda_runtime.h>

#define NN 100000
#define EE 1600000
#define DD 128

// Scratch (allocation-free: device globals)
__device__ float g_aggr[(size_t)NN * DD];
__device__ float g_h[(size_t)NN * DD];
__device__ int g_cnt[NN];
__device__ int g_off[NN + 1];
__device__ int g_fill[NN];
__device__ int g_perm[EE];

// ---------------------------------------------------------------------------
// packed f32x2 helpers (sm_100+)
// ---------------------------------------------------------------------------
__device__ __forceinline__ void fma2(unsigned long long& d, unsigned long long a,
                                     unsigned long long b) {
    asm("fma.rn.f32x2 %0, %1, %2, %3;" : "=l"(d) : "l"(a), "l"(b), "l"(d));
}
__device__ __forceinline__ unsigned long long dup2(float v) {
    unsigned long long r;
    unsigned int u = __float_as_uint(v);
    asm("mov.b64 %0, {%1, %1};" : "=l"(r) : "r"(u));
    return r;
}
__device__ __forceinline__ void unpack2(unsigned long long p, float& lo, float& hi) {
    unsigned int a, b;
    asm("mov.b64 {%0, %1}, %2;" : "=r"(a), "=r"(b) : "l"(p));
    lo = __uint_as_float(a);
    hi = __uint_as_float(b);
}

// ---------------------------------------------------------------------------
// Counting sort of edges by dst
// ---------------------------------------------------------------------------
__global__ void zero_cnt_kernel() {
    int i = blockIdx.x * blockDim.x + threadIdx.x;
    if (i < NN) g_cnt[i] = 0;
}

__global__ void count_kernel(const int* __restrict__ ei) {
    int e = blockIdx.x * blockDim.x + threadIdx.x;
    if (e < EE) atomicAdd(&g_cnt[__ldg(ei + EE + e)], 1);
}

// Single-block exclusive scan of g_cnt -> g_off (and g_fill copy). 1024 threads.
__global__ __launch_bounds__(1024) void scan_kernel() {
    __shared__ int warpsum[32];
    __shared__ int s_carry;
    int tid = threadIdx.x, lane = tid & 31, w = tid >> 5;
    if (tid == 0) s_carry = 0;
    __syncthreads();
    for (int base = 0; base < NN; base += 1024) {
        int i = base + tid;
        int v = (i < NN) ? g_cnt[i] : 0;
        int incl = v;
        #pragma unroll
        for (int o = 1; o < 32; o <<= 1) {
            int t = __shfl_up_sync(0xffffffffu, incl, o);
            if (lane >= o) incl += t;
        }
        if (lane == 31) warpsum[w] = incl;
        __syncthreads();
        if (w == 0) {
            int ws = warpsum[lane];
            int wincl = ws;
            #pragma unroll
            for (int o = 1; o < 32; o <<= 1) {
                int t = __shfl_up_sync(0xffffffffu, wincl, o);
                if (lane >= o) wincl += t;
            }
            warpsum[lane] = wincl - ws;  // exclusive warp prefix
        }
        __syncthreads();
        int excl = incl - v + warpsum[w] + s_carry;
        if (i < NN) {
            g_off[i] = excl;
            g_fill[i] = excl;
        }
        __syncthreads();
        if (tid == 1023) s_carry = excl + v;  // carry = chunk-inclusive total
        __syncthreads();
    }
    if (threadIdx.x == 0) g_off[NN] = s_carry;  // == EE
}

__global__ void fill_kernel(const int* __restrict__ ei) {
    int e = blockIdx.x * blockDim.x + threadIdx.x;
    if (e < EE) {
        int dst = __ldg(ei + EE + e);
        int pos = atomicAdd(&g_fill[dst], 1);
        g_perm[pos] = e;
    }
}

// ---------------------------------------------------------------------------
// Aggregation: one warp per node, register accumulation, single plain store.
// ---------------------------------------------------------------------------
__global__ __launch_bounds__(256) void aggr_kernel(const float* __restrict__ x,
                                                   const int* __restrict__ ei,
                                                   const float* __restrict__ ea) {
    int node = blockIdx.x * 8 + (threadIdx.x >> 5);  // grid covers exactly NN
    int lane = threadIdx.x & 31;
    int beg = __ldg(&g_off[node]);
    int end = __ldg(&g_off[node + 1]);
    float4 acc = make_float4(0.f, 0.f, 0.f, 0.f);

    for (int p0 = beg; p0 < end; p0 += 32) {
        int idx = p0 + lane;
        int e = 0, s = 0;
        if (idx < end) {
            e = __ldg(&g_perm[idx]);
            s = __ldg(ei + e);
        }
        int cnt = min(32, end - p0);
        int t = 0;
        for (; t + 4 <= cnt; t += 4) {
            int e0 = __shfl_sync(0xffffffffu, e, t);
            int e1 = __shfl_sync(0xffffffffu, e, t + 1);
            int e2 = __shfl_sync(0xffffffffu, e, t + 2);
            int e3 = __shfl_sync(0xffffffffu, e, t + 3);
            int s0 = __shfl_sync(0xffffffffu, s, t);
            int s1 = __shfl_sync(0xffffffffu, s, t + 1);
            int s2 = __shfl_sync(0xffffffffu, s, t + 2);
            int s3 = __shfl_sync(0xffffffffu, s, t + 3);
            float4 x0 = __ldg(reinterpret_cast<const float4*>(x) + s0 * 32 + lane);
            float4 a0 = __ldg(reinterpret_cast<const float4*>(ea) + e0 * 32 + lane);
            float4 x1 = __ldg(reinterpret_cast<const float4*>(x) + s1 * 32 + lane);
            float4 a1 = __ldg(reinterpret_cast<const float4*>(ea) + e1 * 32 + lane);
            float4 x2 = __ldg(reinterpret_cast<const float4*>(x) + s2 * 32 + lane);
            float4 a2 = __ldg(reinterpret_cast<const float4*>(ea) + e2 * 32 + lane);
            float4 x3 = __ldg(reinterpret_cast<const float4*>(x) + s3 * 32 + lane);
            float4 a3 = __ldg(reinterpret_cast<const float4*>(ea) + e3 * 32 + lane);
            acc.x += fmaxf(x0.x + a0.x, 0.f); acc.y += fmaxf(x0.y + a0.y, 0.f);
            acc.z += fmaxf(x0.z + a0.z, 0.f); acc.w += fmaxf(x0.w + a0.w, 0.f);
            acc.x += fmaxf(x1.x + a1.x, 0.f); acc.y += fmaxf(x1.y + a1.y, 0.f);
            acc.z += fmaxf(x1.z + a1.z, 0.f); acc.w += fmaxf(x1.w + a1.w, 0.f);
            acc.x += fmaxf(x2.x + a2.x, 0.f); acc.y += fmaxf(x2.y + a2.y, 0.f);
            acc.z += fmaxf(x2.z + a2.z, 0.f); acc.w += fmaxf(x2.w + a2.w, 0.f);
            acc.x += fmaxf(x3.x + a3.x, 0.f); acc.y += fmaxf(x3.y + a3.y, 0.f);
            acc.z += fmaxf(x3.z + a3.z, 0.f); acc.w += fmaxf(x3.w + a3.w, 0.f);
        }
        for (; t < cnt; t++) {
            int et = __shfl_sync(0xffffffffu, e, t);
            int st = __shfl_sync(0xffffffffu, s, t);
            float4 xv = __ldg(reinterpret_cast<const float4*>(x) + st * 32 + lane);
            float4 av = __ldg(reinterpret_cast<const float4*>(ea) + et * 32 + lane);
            acc.x += fmaxf(xv.x + av.x, 0.f); acc.y += fmaxf(xv.y + av.y, 0.f);
            acc.z += fmaxf(xv.z + av.z, 0.f); acc.w += fmaxf(xv.w + av.w, 0.f);
        }
    }
    reinterpret_cast<float4*>(g_aggr)[node * 32 + lane] = acc;
}

// ---------------------------------------------------------------------------
// Register-tiled fp32 GEMM with packed f32x2 FMAs: out[N,128] = act(A' @ W + b)
// ---------------------------------------------------------------------------
template <bool FUSE_Z, bool RELU>
__global__ __launch_bounds__(256, 1) void gemm128(
    const float* __restrict__ A,
    const float* __restrict__ X,
    const float* __restrict__ epsp,
    const float* __restrict__ W,
    const float* __restrict__ bias,
    float* __restrict__ out,
    int nrows) {
    extern __shared__ float smem[];
    float* As = smem;              // [128][128]
    float* Ws = smem + 128 * 128;  // [128][128]

    int tid = threadIdx.x;
    int row0 = blockIdx.x * 128;
    float epsv = 0.f;
    if (FUSE_Z) epsv = 1.0f + __ldg(epsp);

    #pragma unroll
    for (int t = 0; t < 16; t++) {
        int i = tid + t * 256;
        reinterpret_cast<float4*>(Ws)[i] = __ldg(reinterpret_cast<const float4*>(W) + i);
    }
    #pragma unroll
    for (int t = 0; t < 16; t++) {
        int i = tid + t * 256;
        int r = i >> 5;
        int c4 = i & 31;
        int gr = row0 + r;
        float4 v;
        if (gr < nrows) {
            v = __ldg(reinterpret_cast<const float4*>(A) + gr * 32 + c4);
            if (FUSE_Z) {
                float4 xv = __ldg(reinterpret_cast<const float4*>(X) + gr * 32 + c4);
                v.x += epsv * xv.x;
                v.y += epsv * xv.y;
                v.z += epsv * xv.z;
                v.w += epsv * xv.w;
            }
        } else {
            v = make_float4(0.f, 0.f, 0.f, 0.f);
        }
        reinterpret_cast<float4*>(As)[i] = v;
    }
    __syncthreads();

    int tr = tid >> 4;  // 0..15
    int tc = tid & 15;  // 0..15

    unsigned long long acc[8][4];
    #pragma unroll
    for (int i = 0; i < 8; i++)
        #pragma unroll
        for (int j = 0; j < 4; j++) acc[i][j] = 0ull;

    for (int k0 = 0; k0 < 128; k0 += 4) {
        float4 a[8];
        #pragma unroll
        for (int i = 0; i < 8; i++)
            a[i] = *reinterpret_cast<const float4*>(&As[(tr * 8 + i) * 128 + k0]);

        unsigned long long b[4][4];
        #pragma unroll
        for (int kk = 0; kk < 4; kk++) {
            ulonglong2 p0 = *reinterpret_cast<const ulonglong2*>(&Ws[(k0 + kk) * 128 + tc * 4]);
            ulonglong2 p1 = *reinterpret_cast<const ulonglong2*>(&Ws[(k0 + kk) * 128 + 64 + tc * 4]);
            b[kk][0] = p0.x; b[kk][1] = p0.y;
            b[kk][2] = p1.x; b[kk][3] = p1.y;
        }

        #pragma unroll
        for (int kk = 0; kk < 4; kk++) {
            #pragma unroll
            for (int i = 0; i < 8; i++) {
                float av = (kk == 0) ? a[i].x : (kk == 1) ? a[i].y : (kk == 2) ? a[i].z : a[i].w;
                unsigned long long a2 = dup2(av);
                fma2(acc[i][0], a2, b[kk][0]);
                fma2(acc[i][1], a2, b[kk][1]);
                fma2(acc[i][2], a2, b[kk][2]);
                fma2(acc[i][3], a2, b[kk][3]);
            }
        }
    }

    float4 bv0 = __ldg(reinterpret_cast<const float4*>(bias) + tc);
    float4 bv1 = __ldg(reinterpret_cast<const float4*>(bias) + 16 + tc);

    #pragma unroll
    for (int i = 0; i < 8; i++) {
        int gr = row0 + tr * 8 + i;
        if (gr < nrows) {
            float4 o0, o1;
            unpack2(acc[i][0], o0.x, o0.y);
            unpack2(acc[i][1], o0.z, o0.w);
            unpack2(acc[i][2], o1.x, o1.y);
            unpack2(acc[i][3], o1.z, o1.w);
            o0.x += bv0.x; o0.y += bv0.y; o0.z += bv0.z; o0.w += bv0.w;
            o1.x += bv1.x; o1.y += bv1.y; o1.z += bv1.z; o1.w += bv1.w;
            if (RELU) {
                o0.x = fmaxf(o0.x, 0.f); o0.y = fmaxf(o0.y, 0.f);
                o0.z = fmaxf(o0.z, 0.f); o0.w = fmaxf(o0.w, 0.f);
                o1.x = fmaxf(o1.x, 0.f); o1.y = fmaxf(o1.y, 0.f);
                o1.z = fmaxf(o1.z, 0.f); o1.w = fmaxf(o1.w, 0.f);
            }
            reinterpret_cast<float4*>(out)[gr * 32 + tc] = o0;
            reinterpret_cast<float4*>(out)[gr * 32 + 16 + tc] = o1;
        }
    }
}

// ---------------------------------------------------------------------------
extern "C" void kernel_launch(void* const* d_in, const int* in_sizes, int n_in,
                              void* d_out, int out_size) {
    const float* x   = (const float*)d_in[0];
    const int*   ei  = (const int*)d_in[1];
    const float* ea  = (const float*)d_in[2];
    const float* eps = (const float*)d_in[3];
    const float* W1  = (const float*)d_in[4];
    const float* b1  = (const float*)d_in[5];
    const float* W2  = (const float*)d_in[6];
    const float* b2  = (const float*)d_in[7];
    float* out = (float*)d_out;

    float *aggr_p, *h_p;
    cudaGetSymbolAddress((void**)&aggr_p, g_aggr);
    cudaGetSymbolAddress((void**)&h_p, g_h);

    const int SMEM = 2 * 128 * 128 * (int)sizeof(float);  // 131072
    cudaFuncSetAttribute(gemm128<true, true>,
                         cudaFuncAttributeMaxDynamicSharedMemorySize, SMEM);
    cudaFuncSetAttribute(gemm128<false, false>,
                         cudaFuncAttributeMaxDynamicSharedMemorySize, SMEM);

    // 1) counting sort of edges by dst
    zero_cnt_kernel<<<(NN + 255) / 256, 256>>>();
    count_kernel<<<(EE + 255) / 256, 256>>>(ei);
    scan_kernel<<<1, 1024>>>();
    fill_kernel<<<(EE + 255) / 256, 256>>>(ei);

    // 2) gather-aggregate: warp per node, no float atomics
    aggr_kernel<<<NN / 8, 256>>>(x, ei, ea);

    // 3) MLP layer 1: h = relu(((1+eps)x + aggr) @ W1 + b1)
    int nblk = (NN + 127) / 128;
    gemm128<true, true><<<nblk, 256, SMEM>>>(aggr_p, x, eps, W1, b1, h_p, NN);

    // 4) MLP layer 2: out = h @ W2 + b2
    gemm128<false, false><<<nblk, 256, SMEM>>>(h_p, nullptr, nullptr, W2, b2, out, NN);
}

// round 3
// speedup vs baseline: 1.1910x; 1.1535x over previous
#include <cuda_runtime.h>

#define NN 100000
#define EE 1600000
#define DD 128
#define MAXDEG 96
#define OVF_CAP 8192

// Scratch (allocation-free: device globals)
__device__ float g_aggr[(size_t)NN * DD];
__device__ float g_h[(size_t)NN * DD];
__device__ int g_fill[NN];
__device__ int g_perm[(size_t)NN * MAXDEG];
__device__ int g_ovf[OVF_CAP];
__device__ int g_ovf_cnt;

// ---------------------------------------------------------------------------
// packed f32x2 helpers (sm_100+)
// ---------------------------------------------------------------------------
__device__ __forceinline__ void fma2(unsigned long long& d, unsigned long long a,
                                     unsigned long long b) {
    asm("fma.rn.f32x2 %0, %1, %2, %3;" : "=l"(d) : "l"(a), "l"(b), "l"(d));
}
__device__ __forceinline__ unsigned long long dup2(float v) {
    unsigned long long r;
    unsigned int u = __float_as_uint(v);
    asm("mov.b64 %0, {%1, %1};" : "=l"(r) : "r"(u));
    return r;
}
__device__ __forceinline__ void unpack2(unsigned long long p, float& lo, float& hi) {
    unsigned int a, b;
    asm("mov.b64 {%0, %1}, %2;" : "=r"(a), "=r"(b) : "l"(p));
    lo = __uint_as_float(a);
    hi = __uint_as_float(b);
}

// ---------------------------------------------------------------------------
// Slot binning: zero counters, then scatter edge ids into per-node slots.
// ---------------------------------------------------------------------------
__global__ void zero_kernel() {
    int i = blockIdx.x * blockDim.x + threadIdx.x;
    if (i < NN) g_fill[i] = 0;
    if (i == 0) g_ovf_cnt = 0;
}

__global__ void fill_kernel(const int* __restrict__ ei) {
    int e = blockIdx.x * blockDim.x + threadIdx.x;
    if (e < EE) {
        int dst = __ldg(ei + EE + e);
        int pos = atomicAdd(&g_fill[dst], 1);
        if (pos < MAXDEG) {
            g_perm[(size_t)dst * MAXDEG + pos] = e;
        } else {
            int o = atomicAdd(&g_ovf_cnt, 1);
            if (o < OVF_CAP) g_ovf[o] = e;
        }
    }
}

// ---------------------------------------------------------------------------
// Aggregation: one warp per node, register accumulation, single plain store.
// Unroll-by-8 edge batches -> 16 independent 512B warp loads in flight.
// ---------------------------------------------------------------------------
__global__ __launch_bounds__(256) void aggr_kernel(const float* __restrict__ x,
                                                   const int* __restrict__ ei,
                                                   const float* __restrict__ ea) {
    int node = blockIdx.x * 8 + (threadIdx.x >> 5);  // grid covers exactly NN
    int lane = threadIdx.x & 31;
    int cnt = min(__ldg(&g_fill[node]), MAXDEG);
    const int* slots = g_perm + (size_t)node * MAXDEG;
    float4 acc = make_float4(0.f, 0.f, 0.f, 0.f);

    for (int base = 0; base < cnt; base += 32) {
        int m = min(32, cnt - base);
        int e = 0, s = 0;
        if (lane < m) {
            e = __ldg(&slots[base + lane]);
            s = __ldg(ei + e);
        }
        int t = 0;
        for (; t + 8 <= m; t += 8) {
            int eu[8], su[8];
            #pragma unroll
            for (int u = 0; u < 8; u++) {
                eu[u] = __shfl_sync(0xffffffffu, e, t + u);
                su[u] = __shfl_sync(0xffffffffu, s, t + u);
            }
            float4 xv[8], av[8];
            #pragma unroll
            for (int u = 0; u < 8; u++) {
                xv[u] = __ldg(reinterpret_cast<const float4*>(x) + su[u] * 32 + lane);
                av[u] = __ldg(reinterpret_cast<const float4*>(ea) + eu[u] * 32 + lane);
            }
            #pragma unroll
            for (int u = 0; u < 8; u++) {
                acc.x += fmaxf(xv[u].x + av[u].x, 0.f);
                acc.y += fmaxf(xv[u].y + av[u].y, 0.f);
                acc.z += fmaxf(xv[u].z + av[u].z, 0.f);
                acc.w += fmaxf(xv[u].w + av[u].w, 0.f);
            }
        }
        for (; t < m; t++) {
            int et = __shfl_sync(0xffffffffu, e, t);
            int st = __shfl_sync(0xffffffffu, s, t);
            float4 xv = __ldg(reinterpret_cast<const float4*>(x) + st * 32 + lane);
            float4 av = __ldg(reinterpret_cast<const float4*>(ea) + et * 32 + lane);
            acc.x += fmaxf(xv.x + av.x, 0.f);
            acc.y += fmaxf(xv.y + av.y, 0.f);
            acc.z += fmaxf(xv.z + av.z, 0.f);
            acc.w += fmaxf(xv.w + av.w, 0.f);
        }
    }
    reinterpret_cast<float4*>(g_aggr)[node * 32 + lane] = acc;
}

// ---------------------------------------------------------------------------
// Overflow fixup (normally 0 edges): RED-atomic the leftover messages.
// ---------------------------------------------------------------------------
__global__ __launch_bounds__(256) void ovf_kernel(const float* __restrict__ x,
                                                  const int* __restrict__ ei,
                                                  const float* __restrict__ ea) {
    int nov = g_ovf_cnt;
    if (nov > OVF_CAP) nov = OVF_CAP;
    int lane = threadIdx.x & 31;
    int w = blockIdx.x * 8 + (threadIdx.x >> 5);
    for (int i = w; i < nov; i += gridDim.x * 8) {
        int e = g_ovf[i];
        int src = __ldg(ei + e);
        int dst = __ldg(ei + EE + e);
        float4 xv = __ldg(reinterpret_cast<const float4*>(x) + src * 32 + lane);
        float4 av = __ldg(reinterpret_cast<const float4*>(ea) + e * 32 + lane);
        float4 mv;
        mv.x = fmaxf(xv.x + av.x, 0.f);
        mv.y = fmaxf(xv.y + av.y, 0.f);
        mv.z = fmaxf(xv.z + av.z, 0.f);
        mv.w = fmaxf(xv.w + av.w, 0.f);
        float* a = g_aggr + (size_t)dst * DD + lane * 4;
        asm volatile("red.global.add.v4.f32 [%0], {%1, %2, %3, %4};"
                     :: "l"(a), "f"(mv.x), "f"(mv.y), "f"(mv.z), "f"(mv.w)
                     : "memory");
    }
}

// ---------------------------------------------------------------------------
// Register-tiled fp32 GEMM with packed f32x2 FMAs: out[N,128] = act(A' @ W + b)
// ---------------------------------------------------------------------------
template <bool FUSE_Z, bool RELU>
__global__ __launch_bounds__(256, 1) void gemm128(
    const float* __restrict__ A,
    const float* __restrict__ X,
    const float* __restrict__ epsp,
    const float* __restrict__ W,
    const float* __restrict__ bias,
    float* __restrict__ out,
    int nrows) {
    extern __shared__ float smem[];
    float* As = smem;              // [128][128]
    float* Ws = smem + 128 * 128;  // [128][128]

    int tid = threadIdx.x;
    int row0 = blockIdx.x * 128;
    float epsv = 0.f;
    if (FUSE_Z) epsv = 1.0f + __ldg(epsp);

    #pragma unroll
    for (int t = 0; t < 16; t++) {
        int i = tid + t * 256;
        reinterpret_cast<float4*>(Ws)[i] = __ldg(reinterpret_cast<const float4*>(W) + i);
    }
    #pragma unroll
    for (int t = 0; t < 16; t++) {
        int i = tid + t * 256;
        int r = i >> 5;
        int c4 = i & 31;
        int gr = row0 + r;
        float4 v;
        if (gr < nrows) {
            v = __ldg(reinterpret_cast<const float4*>(A) + gr * 32 + c4);
            if (FUSE_Z) {
                float4 xv = __ldg(reinterpret_cast<const float4*>(X) + gr * 32 + c4);
                v.x += epsv * xv.x;
                v.y += epsv * xv.y;
                v.z += epsv * xv.z;
                v.w += epsv * xv.w;
            }
        } else {
            v = make_float4(0.f, 0.f, 0.f, 0.f);
        }
        reinterpret_cast<float4*>(As)[i] = v;
    }
    __syncthreads();

    int tr = tid >> 4;  // 0..15
    int tc = tid & 15;  // 0..15

    unsigned long long acc[8][4];
    #pragma unroll
    for (int i = 0; i < 8; i++)
        #pragma unroll
        for (int j = 0; j < 4; j++) acc[i][j] = 0ull;

    for (int k0 = 0; k0 < 128; k0 += 4) {
        float4 a[8];
        #pragma unroll
        for (int i = 0; i < 8; i++)
            a[i] = *reinterpret_cast<const float4*>(&As[(tr * 8 + i) * 128 + k0]);

        unsigned long long b[4][4];
        #pragma unroll
        for (int kk = 0; kk < 4; kk++) {
            ulonglong2 p0 = *reinterpret_cast<const ulonglong2*>(&Ws[(k0 + kk) * 128 + tc * 4]);
            ulonglong2 p1 = *reinterpret_cast<const ulonglong2*>(&Ws[(k0 + kk) * 128 + 64 + tc * 4]);
            b[kk][0] = p0.x; b[kk][1] = p0.y;
            b[kk][2] = p1.x; b[kk][3] = p1.y;
        }

        #pragma unroll
        for (int kk = 0; kk < 4; kk++) {
            #pragma unroll
            for (int i = 0; i < 8; i++) {
                float av = (kk == 0) ? a[i].x : (kk == 1) ? a[i].y : (kk == 2) ? a[i].z : a[i].w;
                unsigned long long a2 = dup2(av);
                fma2(acc[i][0], a2, b[kk][0]);
                fma2(acc[i][1], a2, b[kk][1]);
                fma2(acc[i][2], a2, b[kk][2]);
                fma2(acc[i][3], a2, b[kk][3]);
            }
        }
    }

    float4 bv0 = __ldg(reinterpret_cast<const float4*>(bias) + tc);
    float4 bv1 = __ldg(reinterpret_cast<const float4*>(bias) + 16 + tc);

    #pragma unroll
    for (int i = 0; i < 8; i++) {
        int gr = row0 + tr * 8 + i;
        if (gr < nrows) {
            float4 o0, o1;
            unpack2(acc[i][0], o0.x, o0.y);
            unpack2(acc[i][1], o0.z, o0.w);
            unpack2(acc[i][2], o1.x, o1.y);
            unpack2(acc[i][3], o1.z, o1.w);
            o0.x += bv0.x; o0.y += bv0.y; o0.z += bv0.z; o0.w += bv0.w;
            o1.x += bv1.x; o1.y += bv1.y; o1.z += bv1.z; o1.w += bv1.w;
            if (RELU) {
                o0.x = fmaxf(o0.x, 0.f); o0.y = fmaxf(o0.y, 0.f);
                o0.z = fmaxf(o0.z, 0.f); o0.w = fmaxf(o0.w, 0.f);
                o1.x = fmaxf(o1.x, 0.f); o1.y = fmaxf(o1.y, 0.f);
                o1.z = fmaxf(o1.z, 0.f); o1.w = fmaxf(o1.w, 0.f);
            }
            reinterpret_cast<float4*>(out)[gr * 32 + tc] = o0;
            reinterpret_cast<float4*>(out)[gr * 32 + 16 + tc] = o1;
        }
    }
}

// ---------------------------------------------------------------------------
extern "C" void kernel_launch(void* const* d_in, const int* in_sizes, int n_in,
                              void* d_out, int out_size) {
    const float* x   = (const float*)d_in[0];
    const int*   ei  = (const int*)d_in[1];
    const float* ea  = (const float*)d_in[2];
    const float* eps = (const float*)d_in[3];
    const float* W1  = (const float*)d_in[4];
    const float* b1  = (const float*)d_in[5];
    const float* W2  = (const float*)d_in[6];
    const float* b2  = (const float*)d_in[7];
    float* out = (float*)d_out;

    float *aggr_p, *h_p;
    cudaGetSymbolAddress((void**)&aggr_p, g_aggr);
    cudaGetSymbolAddress((void**)&h_p, g_h);

    const int SMEM = 2 * 128 * 128 * (int)sizeof(float);  // 131072
    cudaFuncSetAttribute(gemm128<true, true>,
                         cudaFuncAttributeMaxDynamicSharedMemorySize, SMEM);
    cudaFuncSetAttribute(gemm128<false, false>,
                         cudaFuncAttributeMaxDynamicSharedMemorySize, SMEM);

    // 1) slot binning of edges by dst (no count/scan)
    zero_kernel<<<(NN + 255) / 256, 256>>>();
    fill_kernel<<<(EE + 255) / 256, 256>>>(ei);

    // 2) gather-aggregate: warp per node, no float atomics
    aggr_kernel<<<NN / 8, 256>>>(x, ei, ea);

    // 3) overflow fixup (normally empty)
    ovf_kernel<<<4, 256>>>(x, ei, ea);

    // 4) MLP layer 1: h = relu(((1+eps)x + aggr) @ W1 + b1)
    int nblk = (NN + 127) / 128;
    gemm128<true, true><<<nblk, 256, SMEM>>>(aggr_p, x, eps, W1, b1, h_p, NN);

    // 5) MLP layer 2: out = h @ W2 + b2
    gemm128<false, false><<<nblk, 256, SMEM>>>(h_p, nullptr, nullptr, W2, b2, out, NN);
}

// round 4
// speedup vs baseline: 1.3264x; 1.1137x over previous
#include <cuda_runtime.h>

#define NN 100000
#define EE 1600000
#define DD 128
#define MAXDEG 96
#define OVF_CAP 8192

// Scratch (allocation-free: device globals)
__device__ float g_aggr[(size_t)NN * DD];
__device__ int g_fill[NN];
__device__ int2 g_perm2[(size_t)NN * MAXDEG];  // {edge, src}
__device__ int g_ovf[OVF_CAP];
__device__ int g_ovf_cnt;

// ---------------------------------------------------------------------------
// packed f32x2 helpers (sm_100+)
// ---------------------------------------------------------------------------
__device__ __forceinline__ void fma2(unsigned long long& d, unsigned long long a,
                                     unsigned long long b) {
    asm("fma.rn.f32x2 %0, %1, %2, %3;" : "=l"(d) : "l"(a), "l"(b), "l"(d));
}
__device__ __forceinline__ unsigned long long dup2(float v) {
    unsigned long long r;
    unsigned int u = __float_as_uint(v);
    asm("mov.b64 %0, {%1, %1};" : "=l"(r) : "r"(u));
    return r;
}
__device__ __forceinline__ void unpack2(unsigned long long p, float& lo, float& hi) {
    unsigned int a, b;
    asm("mov.b64 {%0, %1}, %2;" : "=r"(a), "=r"(b) : "l"(p));
    lo = __uint_as_float(a);
    hi = __uint_as_float(b);
}

// ---------------------------------------------------------------------------
// Slot binning
// ---------------------------------------------------------------------------
__global__ void zero_kernel() {
    int i = blockIdx.x * blockDim.x + threadIdx.x;
    if (i < NN) g_fill[i] = 0;
    if (i == 0) g_ovf_cnt = 0;
}

__global__ void fill_kernel(const int* __restrict__ ei) {
    int e = blockIdx.x * blockDim.x + threadIdx.x;
    if (e < EE) {
        int dst = __ldg(ei + EE + e);
        int src = __ldg(ei + e);
        int pos = atomicAdd(&g_fill[dst], 1);
        if (pos < MAXDEG) {
            g_perm2[(size_t)dst * MAXDEG + pos] = make_int2(e, src);
        } else {
            int o = atomicAdd(&g_ovf_cnt, 1);
            if (o < OVF_CAP) g_ovf[o] = e;
        }
    }
}

// ---------------------------------------------------------------------------
// Aggregation: warp per node. Unroll-4 (8 loads in flight) + high occupancy.
// ---------------------------------------------------------------------------
__global__ __launch_bounds__(256, 3) void aggr_kernel(const float* __restrict__ x,
                                                      const float* __restrict__ ea) {
    int node = blockIdx.x * 8 + (threadIdx.x >> 5);  // grid covers exactly NN
    int lane = threadIdx.x & 31;
    int cnt = min(__ldg(&g_fill[node]), MAXDEG);
    const int2* slots = g_perm2 + (size_t)node * MAXDEG;
    float4 acc = make_float4(0.f, 0.f, 0.f, 0.f);

    for (int base = 0; base < cnt; base += 32) {
        int m = min(32, cnt - base);
        int2 es = make_int2(0, 0);
        if (lane < m) es = __ldg(&slots[base + lane]);
        int t = 0;
        for (; t + 4 <= m; t += 4) {
            int eu[4], su[4];
            #pragma unroll
            for (int u = 0; u < 4; u++) {
                eu[u] = __shfl_sync(0xffffffffu, es.x, t + u);
                su[u] = __shfl_sync(0xffffffffu, es.y, t + u);
            }
            float4 xv[4], av[4];
            #pragma unroll
            for (int u = 0; u < 4; u++) {
                xv[u] = __ldg(reinterpret_cast<const float4*>(x) + su[u] * 32 + lane);
                av[u] = __ldg(reinterpret_cast<const float4*>(ea) + eu[u] * 32 + lane);
            }
            #pragma unroll
            for (int u = 0; u < 4; u++) {
                acc.x += fmaxf(xv[u].x + av[u].x, 0.f);
                acc.y += fmaxf(xv[u].y + av[u].y, 0.f);
                acc.z += fmaxf(xv[u].z + av[u].z, 0.f);
                acc.w += fmaxf(xv[u].w + av[u].w, 0.f);
            }
        }
        for (; t < m; t++) {
            int et = __shfl_sync(0xffffffffu, es.x, t);
            int st = __shfl_sync(0xffffffffu, es.y, t);
            float4 xv = __ldg(reinterpret_cast<const float4*>(x) + st * 32 + lane);
            float4 av = __ldg(reinterpret_cast<const float4*>(ea) + et * 32 + lane);
            acc.x += fmaxf(xv.x + av.x, 0.f);
            acc.y += fmaxf(xv.y + av.y, 0.f);
            acc.z += fmaxf(xv.z + av.z, 0.f);
            acc.w += fmaxf(xv.w + av.w, 0.f);
        }
    }
    reinterpret_cast<float4*>(g_aggr)[node * 32 + lane] = acc;
}

// ---------------------------------------------------------------------------
// Overflow fixup (normally 0 edges)
// ---------------------------------------------------------------------------
__global__ __launch_bounds__(256) void ovf_kernel(const float* __restrict__ x,
                                                  const int* __restrict__ ei,
                                                  const float* __restrict__ ea) {
    int nov = g_ovf_cnt;
    if (nov > OVF_CAP) nov = OVF_CAP;
    int lane = threadIdx.x & 31;
    int w = blockIdx.x * 8 + (threadIdx.x >> 5);
    for (int i = w; i < nov; i += gridDim.x * 8) {
        int e = g_ovf[i];
        int src = __ldg(ei + e);
        int dst = __ldg(ei + EE + e);
        float4 xv = __ldg(reinterpret_cast<const float4*>(x) + src * 32 + lane);
        float4 av = __ldg(reinterpret_cast<const float4*>(ea) + e * 32 + lane);
        float4 mv;
        mv.x = fmaxf(xv.x + av.x, 0.f);
        mv.y = fmaxf(xv.y + av.y, 0.f);
        mv.z = fmaxf(xv.z + av.z, 0.f);
        mv.w = fmaxf(xv.w + av.w, 0.f);
        float* a = g_aggr + (size_t)dst * DD + lane * 4;
        asm volatile("red.global.add.v4.f32 [%0], {%1, %2, %3, %4};"
                     :: "l"(a), "f"(mv.x), "f"(mv.y), "f"(mv.z), "f"(mv.w)
                     : "memory");
    }
}

// ---------------------------------------------------------------------------
// Fused 2-layer MLP, 128-row tile per CTA, f32x2 FMAs.
// out = relu(((1+eps)x + aggr) @ W1 + b1) @ W2 + b2
// ---------------------------------------------------------------------------
__global__ __launch_bounds__(256, 1) void mlp_fused(
    const float* __restrict__ A,     // g_aggr
    const float* __restrict__ X,
    const float* __restrict__ epsp,
    const float* __restrict__ W1,
    const float* __restrict__ b1,
    const float* __restrict__ W2,
    const float* __restrict__ b2,
    float* __restrict__ out,
    int nrows) {
    extern __shared__ float smem[];
    float* As = smem;              // [128][128]  (A', then h in-place)
    float* Ws = smem + 128 * 128;  // [128][128]  (W1, then W2)

    int tid = threadIdx.x;
    int row0 = blockIdx.x * 128;
    float epsv = 1.0f + __ldg(epsp);

    // Load W1
    #pragma unroll
    for (int t = 0; t < 16; t++) {
        int i = tid + t * 256;
        reinterpret_cast<float4*>(Ws)[i] = __ldg(reinterpret_cast<const float4*>(W1) + i);
    }
    // Load A' = (1+eps)x + aggr
    #pragma unroll
    for (int t = 0; t < 16; t++) {
        int i = tid + t * 256;
        int r = i >> 5;
        int c4 = i & 31;
        int gr = row0 + r;
        float4 v;
        if (gr < nrows) {
            v = __ldg(reinterpret_cast<const float4*>(A) + gr * 32 + c4);
            float4 xv = __ldg(reinterpret_cast<const float4*>(X) + gr * 32 + c4);
            v.x += epsv * xv.x;
            v.y += epsv * xv.y;
            v.z += epsv * xv.z;
            v.w += epsv * xv.w;
        } else {
            v = make_float4(0.f, 0.f, 0.f, 0.f);
        }
        reinterpret_cast<float4*>(As)[i] = v;
    }
    __syncthreads();

    int tr = tid >> 4;  // 0..15
    int tc = tid & 15;  // 0..15

    // ---- Layer 1 ----
    unsigned long long acc[8][4];
    #pragma unroll
    for (int i = 0; i < 8; i++)
        #pragma unroll
        for (int j = 0; j < 4; j++) acc[i][j] = 0ull;

    for (int k0 = 0; k0 < 128; k0 += 4) {
        float4 a[8];
        #pragma unroll
        for (int i = 0; i < 8; i++)
            a[i] = *reinterpret_cast<const float4*>(&As[(tr * 8 + i) * 128 + k0]);
        unsigned long long b[4][4];
        #pragma unroll
        for (int kk = 0; kk < 4; kk++) {
            ulonglong2 p0 = *reinterpret_cast<const ulonglong2*>(&Ws[(k0 + kk) * 128 + tc * 4]);
            ulonglong2 p1 = *reinterpret_cast<const ulonglong2*>(&Ws[(k0 + kk) * 128 + 64 + tc * 4]);
            b[kk][0] = p0.x; b[kk][1] = p0.y;
            b[kk][2] = p1.x; b[kk][3] = p1.y;
        }
        #pragma unroll
        for (int kk = 0; kk < 4; kk++) {
            #pragma unroll
            for (int i = 0; i < 8; i++) {
                float av = (kk == 0) ? a[i].x : (kk == 1) ? a[i].y : (kk == 2) ? a[i].z : a[i].w;
                unsigned long long a2 = dup2(av);
                fma2(acc[i][0], a2, b[kk][0]);
                fma2(acc[i][1], a2, b[kk][1]);
                fma2(acc[i][2], a2, b[kk][2]);
                fma2(acc[i][3], a2, b[kk][3]);
            }
        }
    }
    __syncthreads();  // all reads of As/Ws done

    // Epilogue 1: h = relu(acc + b1) -> As (in place), W2 -> Ws
    {
        float4 bv0 = __ldg(reinterpret_cast<const float4*>(b1) + tc);
        float4 bv1 = __ldg(reinterpret_cast<const float4*>(b1) + 16 + tc);
        #pragma unroll
        for (int i = 0; i < 8; i++) {
            float4 o0, o1;
            unpack2(acc[i][0], o0.x, o0.y);
            unpack2(acc[i][1], o0.z, o0.w);
            unpack2(acc[i][2], o1.x, o1.y);
            unpack2(acc[i][3], o1.z, o1.w);
            o0.x = fmaxf(o0.x + bv0.x, 0.f); o0.y = fmaxf(o0.y + bv0.y, 0.f);
            o0.z = fmaxf(o0.z + bv0.z, 0.f); o0.w = fmaxf(o0.w + bv0.w, 0.f);
            o1.x = fmaxf(o1.x + bv1.x, 0.f); o1.y = fmaxf(o1.y + bv1.y, 0.f);
            o1.z = fmaxf(o1.z + bv1.z, 0.f); o1.w = fmaxf(o1.w + bv1.w, 0.f);
            *reinterpret_cast<float4*>(&As[(tr * 8 + i) * 128 + tc * 4]) = o0;
            *reinterpret_cast<float4*>(&As[(tr * 8 + i) * 128 + 64 + tc * 4]) = o1;
        }
        #pragma unroll
        for (int t = 0; t < 16; t++) {
            int i = tid + t * 256;
            reinterpret_cast<float4*>(Ws)[i] = __ldg(reinterpret_cast<const float4*>(W2) + i);
        }
    }
    __syncthreads();

    // ---- Layer 2 ----
    #pragma unroll
    for (int i = 0; i < 8; i++)
        #pragma unroll
        for (int j = 0; j < 4; j++) acc[i][j] = 0ull;

    for (int k0 = 0; k0 < 128; k0 += 4) {
        float4 a[8];
        #pragma unroll
        for (int i = 0; i < 8; i++)
            a[i] = *reinterpret_cast<const float4*>(&As[(tr * 8 + i) * 128 + k0]);
        unsigned long long b[4][4];
        #pragma unroll
        for (int kk = 0; kk < 4; kk++) {
            ulonglong2 p0 = *reinterpret_cast<const ulonglong2*>(&Ws[(k0 + kk) * 128 + tc * 4]);
            ulonglong2 p1 = *reinterpret_cast<const ulonglong2*>(&Ws[(k0 + kk) * 128 + 64 + tc * 4]);
            b[kk][0] = p0.x; b[kk][1] = p0.y;
            b[kk][2] = p1.x; b[kk][3] = p1.y;
        }
        #pragma unroll
        for (int kk = 0; kk < 4; kk++) {
            #pragma unroll
            for (int i = 0; i < 8; i++) {
                float av = (kk == 0) ? a[i].x : (kk == 1) ? a[i].y : (kk == 2) ? a[i].z : a[i].w;
                unsigned long long a2 = dup2(av);
                fma2(acc[i][0], a2, b[kk][0]);
                fma2(acc[i][1], a2, b[kk][1]);
                fma2(acc[i][2], a2, b[kk][2]);
                fma2(acc[i][3], a2, b[kk][3]);
            }
        }
    }

    float4 bv0 = __ldg(reinterpret_cast<const float4*>(b2) + tc);
    float4 bv1 = __ldg(reinterpret_cast<const float4*>(b2) + 16 + tc);
    #pragma unroll
    for (int i = 0; i < 8; i++) {
        int gr = row0 + tr * 8 + i;
        if (gr < nrows) {
            float4 o0, o1;
            unpack2(acc[i][0], o0.x, o0.y);
            unpack2(acc[i][1], o0.z, o0.w);
            unpack2(acc[i][2], o1.x, o1.y);
            unpack2(acc[i][3], o1.z, o1.w);
            o0.x += bv0.x; o0.y += bv0.y; o0.z += bv0.z; o0.w += bv0.w;
            o1.x += bv1.x; o1.y += bv1.y; o1.z += bv1.z; o1.w += bv1.w;
            reinterpret_cast<float4*>(out)[gr * 32 + tc] = o0;
            reinterpret_cast<float4*>(out)[gr * 32 + 16 + tc] = o1;
        }
    }
}

// ---------------------------------------------------------------------------
extern "C" void kernel_launch(void* const* d_in, const int* in_sizes, int n_in,
                              void* d_out, int out_size) {
    const float* x   = (const float*)d_in[0];
    const int*   ei  = (const int*)d_in[1];
    const float* ea  = (const float*)d_in[2];
    const float* eps = (const float*)d_in[3];
    const float* W1  = (const float*)d_in[4];
    const float* b1  = (const float*)d_in[5];
    const float* W2  = (const float*)d_in[6];
    const float* b2  = (const float*)d_in[7];
    float* out = (float*)d_out;

    float* aggr_p;
    cudaGetSymbolAddress((void**)&aggr_p, g_aggr);

    const int SMEM = 2 * 128 * 128 * (int)sizeof(float);  // 131072
    cudaFuncSetAttribute(mlp_fused, cudaFuncAttributeMaxDynamicSharedMemorySize, SMEM);

    // 1) slot binning of edges by dst
    zero_kernel<<<(NN + 255) / 256, 256>>>();
    fill_kernel<<<(EE + 255) / 256, 256>>>(ei);

    // 2) gather-aggregate: warp per node, no float atomics
    aggr_kernel<<<NN / 8, 256>>>(x, ea);

    // 3) overflow fixup (normally empty)
    ovf_kernel<<<4, 256>>>(x, ei, ea);

    // 4) fused 2-layer MLP
    int nblk = (NN + 127) / 128;
    mlp_fused<<<nblk, 256, SMEM>>>(aggr_p, x, eps, W1, b1, W2, b2, out, NN);
}